// round 14
// baseline (speedup 1.0000x reference)
#include <cuda_runtime.h>
#include <cuda_fp16.h>
#include <cstdint>

// Problem shape constants (fixed by the reference).
#define BB 2
#define LL 2048
#define DD 1024
#define HH 16
#define HD 64
#define ROWS (BB*LL)            // 4096
#define QKV_N (3*DD)            // 3072
#define BLD (BB*LL*DD)          // 4194304
#define WQKV_SZ (QKV_N*DD)      // 3145728
#define WOUT_SZ (DD*DD)         // 1048576

// ---------------------------------------------------------------------------
// Scratch (alloc-free rule: __device__ globals)
// ---------------------------------------------------------------------------
__device__ __half g_xr  [BLD];            // x -> fp16
__device__ __half g_wqkv[WQKV_SZ];        // Wqkv -> fp16
__device__ __half g_wout[WOUT_SZ];        // Wout -> fp16
__device__ float  g_qkv [ROWS * QKV_N];   // qkv projection (fp32 accum)
__device__ __half g_q   [BLD];            // q heads, rope'd, scaled, fp16
__device__ __half g_k   [BLD];            // k heads, rope'd, fp16
__device__ __half g_v   [BLD];            // v heads, fp16
__device__ __half g_ctx [BLD];            // attention context, fp16

// ---------------------------------------------------------------------------
// Helpers
// ---------------------------------------------------------------------------
__device__ __forceinline__ uint32_t smem_u32(const void* p) {
    uint32_t a;
    asm("{ .reg .u64 t; cvta.to.shared.u64 t, %1; cvt.u32.u64 %0, t; }"
        : "=r"(a) : "l"(p));
    return a;
}

// m16n8k16 fp16 mma, fp32 accumulate (.row.col)
__device__ __forceinline__ void mma16(float* c, const uint32_t* a, const uint32_t* b) {
    asm volatile(
        "mma.sync.aligned.m16n8k16.row.col.f32.f16.f16.f32 "
        "{%0,%1,%2,%3}, {%4,%5,%6,%7}, {%8,%9}, {%0,%1,%2,%3};"
        : "+f"(c[0]), "+f"(c[1]), "+f"(c[2]), "+f"(c[3])
        : "r"(a[0]), "r"(a[1]), "r"(a[2]), "r"(a[3]), "r"(b[0]), "r"(b[1]));
}

// ldmatrix x4 b16
__device__ __forceinline__ void ldsm4(uint32_t* r, uint32_t addr) {
    asm volatile(
        "ldmatrix.sync.aligned.m8n8.x4.shared.b16 {%0,%1,%2,%3}, [%4];"
        : "=r"(r[0]), "=r"(r[1]), "=r"(r[2]), "=r"(r[3]) : "r"(addr));
}

// ldmatrix x4 b16 transposed (for V: row-major smem -> col-major fragment)
__device__ __forceinline__ void ldsm4t(uint32_t* r, uint32_t addr) {
    asm volatile(
        "ldmatrix.sync.aligned.m8n8.x4.trans.shared.b16 {%0,%1,%2,%3}, [%4];"
        : "=r"(r[0]), "=r"(r[1]), "=r"(r[2]), "=r"(r[3]) : "r"(addr));
}

__device__ __forceinline__ uint32_t pack_h2(float a, float b) {
    __half2 h = __floats2half2_rn(a, b);
    return *(uint32_t*)&h;
}

#define CP16(dst, src) \
    asm volatile("cp.async.cg.shared.global [%0], [%1], 16;" :: "r"(dst), "l"(src))
#define CP_COMMIT() asm volatile("cp.async.commit_group;" ::: "memory")
#define CP_WAIT(n)  asm volatile("cp.async.wait_group %0;" :: "n"(n) : "memory")

// ---------------------------------------------------------------------------
// Fused fp32 -> fp16 conversion of x, Wqkv, Wout
// ---------------------------------------------------------------------------
#define RND_TOTAL4 ((BLD + WQKV_SZ + WOUT_SZ) / 4)

__global__ __launch_bounds__(256) void round_all(
    const float4* __restrict__ x,   __half* __restrict__ xr,
    const float4* __restrict__ wq,  __half* __restrict__ wqr,
    const float4* __restrict__ wo,  __half* __restrict__ wor)
{
    int i = blockIdx.x * 256 + threadIdx.x;
    if (i >= RND_TOTAL4) return;
    const float4* src; __half* dst;
    if (i < BLD/4)                       { src = x;  dst = xr;  }
    else if (i < (BLD + WQKV_SZ)/4)      { src = wq; dst = wqr; i -= BLD/4; }
    else                                 { src = wo; dst = wor; i -= (BLD + WQKV_SZ)/4; }
    float4 v = src[i];
    uint2 o;
    o.x = pack_h2(v.x, v.y);
    o.y = pack_h2(v.z, v.w);
    *(uint2*)(dst + (size_t)i * 4) = o;
}

// ---------------------------------------------------------------------------
// fp16 mma.sync NT GEMM, 3-stage cp.async pipeline.
// 128x128 CTA tile, BK=32 halves, 256 threads (8 warps, 2x4 of 64x32 tiles).
// smem rows padded to 40 halves (80B = 5*16B -> ldmatrix conflict-free).
// ---------------------------------------------------------------------------
#define HSTR 40
#define GEMM_TILE_B (128 * HSTR * 2)          // 10240 B per matrix per stage
#define GEMM_STAGES 3
#define GEMM_SMEM   (2 * GEMM_STAGES * GEMM_TILE_B)   // 61440 B

__global__ __launch_bounds__(256) void gemm_mma(
    const __half* __restrict__ A, const __half* __restrict__ B,
    const float* __restrict__ bias, float* __restrict__ C,
    int N, int K)
{
    extern __shared__ char smraw[];
    const uint32_t As_u = smem_u32(smraw);
    const uint32_t Bs_u = As_u + GEMM_STAGES * GEMM_TILE_B;

    const int tid  = threadIdx.x;
    const int lane = tid & 31;
    const int wid  = tid >> 5;
    const int wm   = wid & 1;
    const int wn   = wid >> 1;
    const int lq   = lane >> 2;
    const int ls   = lane & 3;
    const int s    = lane >> 3;
    const int srow = lane & 7;

    const uint32_t a_lane =
        (uint32_t)(wm * 64 + (s & 1) * 8 + srow) * (HSTR * 2) + (s >> 1) * 16;
    const uint32_t b_lane =
        (uint32_t)(wn * 32 + (s >> 1) * 8 + srow) * (HSTR * 2) + (s & 1) * 16;

    const __half* Ab = A + (size_t)(blockIdx.y * 128) * K;
    const __half* Bb = B + (size_t)(blockIdx.x * 128) * K;
    const int KS = K >> 5;

    float acc[4][4][4];
#pragma unroll
    for (int mt = 0; mt < 4; ++mt)
#pragma unroll
        for (int nt = 0; nt < 4; ++nt)
#pragma unroll
            for (int r = 0; r < 4; ++r) acc[mt][nt][r] = 0.f;

#define GEMM_LOAD(ks, stg)                                                    \
    {                                                                         \
        const int k0 = (ks) * 32;                                             \
        const uint32_t dA = As_u + (stg) * GEMM_TILE_B;                       \
        const uint32_t dB = Bs_u + (stg) * GEMM_TILE_B;                       \
        _Pragma("unroll")                                                     \
        for (int i = 0; i < 2; ++i) {                                         \
            const int c   = tid + i * 256;                                    \
            const int row = c >> 2;                                           \
            const int cc  = (c & 3) * 8;                                      \
            const uint32_t off = (uint32_t)row * (HSTR * 2) + cc * 2;         \
            CP16(dA + off, Ab + (size_t)row * K + k0 + cc);                   \
            CP16(dB + off, Bb + (size_t)row * K + k0 + cc);                   \
        }                                                                     \
        CP_COMMIT();                                                          \
    }

    GEMM_LOAD(0, 0);
    GEMM_LOAD(1, 1);

    int db = 0, nb = 2;
    for (int ks = 0; ks < KS; ++ks) {
        CP_WAIT(1);                      // stage ks arrived (<=1 in flight)
        __syncthreads();                 // all warps done with stage (ks-1)

        if (ks + 2 < KS) {               // prefetch into stage (ks-1)%3
            GEMM_LOAD(ks + 2, nb);
            nb = (nb + 1 == GEMM_STAGES) ? 0 : nb + 1;
        }

        const uint32_t Ad_u = As_u + db * GEMM_TILE_B;
        const uint32_t Bd_u = Bs_u + db * GEMM_TILE_B;

#pragma unroll
        for (int kk = 0; kk < 2; ++kk) {
            uint32_t a[4][4], b[2][4];
#pragma unroll
            for (int mt = 0; mt < 4; ++mt)
                ldsm4(a[mt], Ad_u + a_lane +
                      (uint32_t)(mt * 16 * HSTR * 2 + kk * 32));
#pragma unroll
            for (int ntp = 0; ntp < 2; ++ntp)
                ldsm4(b[ntp], Bd_u + b_lane +
                      (uint32_t)(ntp * 16 * HSTR * 2 + kk * 32));
#pragma unroll
            for (int mt = 0; mt < 4; ++mt)
#pragma unroll
                for (int nt = 0; nt < 4; ++nt)
                    mma16(acc[mt][nt], a[mt], &b[nt >> 1][(nt & 1) * 2]);
        }
        db = (db + 1 == GEMM_STAGES) ? 0 : db + 1;
    }

    const int row_base = blockIdx.y * 128 + wm * 64;
    const int col_base = blockIdx.x * 128 + wn * 32;
#pragma unroll
    for (int mt = 0; mt < 4; ++mt) {
        const int r0 = row_base + mt * 16 + lq;
#pragma unroll
        for (int nt = 0; nt < 4; ++nt) {
            const int cn = col_base + nt * 8 + ls * 2;
            const float2 bb = *(const float2*)(bias + cn);
            float2 o0, o1;
            o0.x = acc[mt][nt][0] + bb.x;  o0.y = acc[mt][nt][1] + bb.y;
            o1.x = acc[mt][nt][2] + bb.x;  o1.y = acc[mt][nt][3] + bb.y;
            *(float2*)(C + (size_t)r0 * N + cn)       = o0;
            *(float2*)(C + (size_t)(r0 + 8) * N + cn) = o1;
        }
    }
}

// ---------------------------------------------------------------------------
// RoPE + head scatter (unchanged).
// ---------------------------------------------------------------------------
__global__ __launch_bounds__(256) void rope_scatter(
    const float* __restrict__ qkv,
    __half* __restrict__ qh, __half* __restrict__ kh, __half* __restrict__ vh,
    float* __restrict__ kout, float* __restrict__ vout)
{
    const int t = blockIdx.x * blockDim.x + threadIdx.x;
    const int d = t & 31;
    const int h = (t >> 5) & 15;
    const int l = (t >> 9) & 2047;
    const int b = t >> 20;

    const float* base = qkv + (size_t)(b * LL + l) * QKV_N;

    const float inv = __expf(-(float)d * (9.210340371976184f / 32.f));
    const float ang = (float)l * inv;
    float sn, cs;
    sincosf(ang, &sn, &cs);

    const size_t ob = ((size_t)((b * HH + h) * LL + l)) * HD;

    const float q1 = base[h*HD + d], q2 = base[h*HD + d + 32];
    qh[ob + d]      = __float2half_rn((q1 * cs - q2 * sn) * 0.125f);
    qh[ob + d + 32] = __float2half_rn((q1 * sn + q2 * cs) * 0.125f);

    const float k1 = base[DD + h*HD + d], k2 = base[DD + h*HD + d + 32];
    const float kr1 = k1 * cs - k2 * sn;
    const float kr2 = k1 * sn + k2 * cs;
    kout[ob + d]      = kr1;
    kout[ob + d + 32] = kr2;
    kh[ob + d]        = __float2half_rn(kr1);
    kh[ob + d + 32]   = __float2half_rn(kr2);

    const float v1 = base[2*DD + h*HD + d], v2 = base[2*DD + h*HD + d + 32];
    vout[ob + d]      = v1;
    vout[ob + d + 32] = v2;
    vh[ob + d]        = __float2half_rn(v1);
    vh[ob + d + 32]   = __float2half_rn(v2);
}

// ---------------------------------------------------------------------------
// Flash attention v11 (fp16, register-P, ldmatrix.trans V, lazy rescale):
// Br=128, Bc=64, 256 threads (8 warps = 4 row-groups x 2 col-groups).
// smem bytes: Ks[2][64*72h]=18432 | Vs[2][64*72h]=18432 | cm[2][128]f=1024 |
//             cl[2][128]f=1024    total 38912.
// Epilogue 'ac' (128 x 66 fp32 = 33792 B) aliases Ks+Vs (dead by then).
// ---------------------------------------------------------------------------
#define KSTRB 144                     // 72 halves per row
#define FKS_B  (64 * KSTRB)           // 9216 per K/V buffer
#define FVT_O  (2 * FKS_B)            // 18432
#define FCM_O  (FVT_O + 2 * FKS_B)    // 36864
#define FCL_O  (FCM_O + 1024)         // 37888
#define FLASH_SMEM (FCL_O + 1024)     // 38912 B

__global__ __launch_bounds__(256) void flash_mma(
    const __half* __restrict__ Q, const __half* __restrict__ K,
    const __half* __restrict__ V, __half* __restrict__ ctx)
{
    extern __shared__ char smraw[];
    float*  cm = (float*)(smraw + FCM_O);   // [2][128]
    float*  cl = (float*)(smraw + FCL_O);   // [2][128]
    float*  ac = (float*)smraw;             // epilogue alias, stride 66
    const uint32_t Ks_u = smem_u32(smraw);
    const uint32_t Vs_u = Ks_u + FVT_O;

    const int qi   = gridDim.x - 1 - blockIdx.x;   // heavy tiles first
    const int bh   = blockIdx.y;
    const int tid  = threadIdx.x;
    const int lane = tid & 31;
    const int wid  = tid >> 5;           // 0..7
    const int wr   = wid & 3;            // row group (4 x 32 rows)
    const int wc   = wid >> 2;           // col group (2 x 32 tokens)
    const int lq   = lane >> 2;
    const int ls   = lane & 3;
    const int s    = lane >> 3;
    const int srow = lane & 7;
    const int row0 = wr * 32;

    const uint32_t bk_lane =
        (uint32_t)((s >> 1) * 8 + srow) * KSTRB + (s & 1) * 16;
    const uint32_t bv_lane =
        (uint32_t)((s & 1) * 8 + srow) * KSTRB + (s >> 1) * 16;

    const __half* Qb = Q + ((size_t)bh * LL + qi * 128) * HD;
    const __half* Kb = K + (size_t)bh * LL * HD;
    const __half* Vb = V + (size_t)bh * LL * HD;

#define FL_LOAD_T(dst_u, src)                                                 \
    {                                                                         \
        _Pragma("unroll")                                                     \
        for (int i = 0; i < 2; ++i) {                                         \
            const int c   = tid + i * 256;                                    \
            const int row = c >> 3;                                           \
            const int cc  = (c & 7) * 8;                                      \
            CP16((dst_u) + (uint32_t)row * KSTRB + cc * 2,                    \
                 (src) + (size_t)row * HD + cc);                              \
        }                                                                     \
    }

    // prologue: K0 + V0 in one cp.async group
    FL_LOAD_T(Ks_u, Kb);
    FL_LOAD_T(Vs_u, Vb);
    CP_COMMIT();

    uint32_t qf[4][2][4];
#pragma unroll
    for (int ks = 0; ks < 4; ++ks) {
#pragma unroll
        for (int mt = 0; mt < 2; ++mt) {
            const int r = row0 + mt * 16 + lq;
            const __half* q0 = Qb + (size_t)r * HD + ks * 16;
            const __half* q1 = Qb + (size_t)(r + 8) * HD + ks * 16;
            qf[ks][mt][0] = *(const uint32_t*)(q0 + 2 * ls);
            qf[ks][mt][1] = *(const uint32_t*)(q1 + 2 * ls);
            qf[ks][mt][2] = *(const uint32_t*)(q0 + 8 + 2 * ls);
            qf[ks][mt][3] = *(const uint32_t*)(q1 + 8 + 2 * ls);
        }
    }

    float acc[2][8][4];
#pragma unroll
    for (int mt = 0; mt < 2; ++mt)
#pragma unroll
        for (int nt = 0; nt < 8; ++nt)
#pragma unroll
            for (int r = 0; r < 4; ++r) acc[mt][nt][r] = 0.f;
    float mm[4] = {-1e30f, -1e30f, -1e30f, -1e30f};
    float llv[4] = {0.f, 0.f, 0.f, 0.f};

    const int jtmax = 2 * qi + 1;

    for (int jt = 0; jt <= jtmax; ++jt) {
        const int db = jt & 1;
        CP_WAIT(0);
        __syncthreads();                 // K_jt/V_jt visible; db^1 reads done

        if (jt < jtmax) {
            FL_LOAD_T(Ks_u + (uint32_t)((db ^ 1) * FKS_B),
                      Kb + (size_t)(jt + 1) * 64 * HD);
            FL_LOAD_T(Vs_u + (uint32_t)((db ^ 1) * FKS_B),
                      Vb + (size_t)(jt + 1) * 64 * HD);
            CP_COMMIT();
        }

        // ---- S = Q K^T on this warp's 32 tokens ----
        float sc[2][4][4];
#pragma unroll
        for (int mt = 0; mt < 2; ++mt)
#pragma unroll
            for (int nt = 0; nt < 4; ++nt)
#pragma unroll
                for (int r = 0; r < 4; ++r) sc[mt][nt][r] = 0.f;

        const uint32_t Kd_u = Ks_u + (uint32_t)(db * FKS_B)
                            + (uint32_t)(wc * 32) * KSTRB + bk_lane;
#pragma unroll
        for (int ks = 0; ks < 4; ++ks) {
#pragma unroll
            for (int ntp = 0; ntp < 2; ++ntp) {
                uint32_t b[4];
                ldsm4(b, Kd_u + (uint32_t)(ntp * 16) * KSTRB + ks * 32);
#pragma unroll
                for (int mt = 0; mt < 2; ++mt) {
                    mma16(sc[mt][ntp * 2],     qf[ks][mt], b);
                    mma16(sc[mt][ntp * 2 + 1], qf[ks][mt], b + 2);
                }
            }
        }

        // ---- causal mask (last two tiles) ----
        if (jt >= 2 * qi) {
            const int cbase = jt * 64 + wc * 32;
#pragma unroll
            for (int mt = 0; mt < 2; ++mt) {
                const int rg0 = qi * 128 + row0 + mt * 16 + lq;
#pragma unroll
                for (int nt = 0; nt < 4; ++nt) {
                    const int cg = cbase + nt * 8 + ls * 2;
                    if (cg > rg0)         sc[mt][nt][0] += -1000000000.0f;
                    if (cg + 1 > rg0)     sc[mt][nt][1] += -1000000000.0f;
                    if (cg > rg0 + 8)     sc[mt][nt][2] += -1000000000.0f;
                    if (cg + 1 > rg0 + 8) sc[mt][nt][3] += -1000000000.0f;
                }
            }
        }

        // ---- row max per row-pair group (quad shfl) ----
        float mx[4];
#pragma unroll
        for (int mt = 0; mt < 2; ++mt) {
            float a0 = sc[mt][0][0], a1 = sc[mt][0][2];
#pragma unroll
            for (int nt = 0; nt < 4; ++nt) {
                a0 = fmaxf(a0, fmaxf(sc[mt][nt][0], sc[mt][nt][1]));
                a1 = fmaxf(a1, fmaxf(sc[mt][nt][2], sc[mt][nt][3]));
            }
            mx[mt * 2]     = a0;
            mx[mt * 2 + 1] = a1;
        }
#pragma unroll
        for (int i = 0; i < 4; ++i) {
            mx[i] = fmaxf(mx[i], __shfl_xor_sync(0xffffffffu, mx[i], 1));
            mx[i] = fmaxf(mx[i], __shfl_xor_sync(0xffffffffu, mx[i], 2));
        }

        float al[4];
        bool need_rescale = false;
#pragma unroll
        for (int i = 0; i < 4; ++i) {
            const float mn = fmaxf(mm[i], mx[i]);
            al[i] = __expf(mm[i] - mn);
            need_rescale |= (mn != mm[i]);
            mm[i] = mn;
        }

        // ---- P = exp(S - m): pack straight into PV A-fragments ----
        uint32_t pa[2][2][4];
        float rs[4] = {0.f, 0.f, 0.f, 0.f};
#pragma unroll
        for (int mt = 0; mt < 2; ++mt) {
            const float mn0 = mm[mt * 2], mn1 = mm[mt * 2 + 1];
#pragma unroll
            for (int nt = 0; nt < 4; ++nt) {
                const float p0 = __expf(sc[mt][nt][0] - mn0);
                const float p1 = __expf(sc[mt][nt][1] - mn0);
                const float p2 = __expf(sc[mt][nt][2] - mn1);
                const float p3 = __expf(sc[mt][nt][3] - mn1);
                rs[mt * 2]     += p0 + p1;
                rs[mt * 2 + 1] += p2 + p3;
                pa[mt][nt >> 1][(nt & 1) * 2 + 0] = pack_h2(p0, p1);
                pa[mt][nt >> 1][(nt & 1) * 2 + 1] = pack_h2(p2, p3);
            }
        }
#pragma unroll
        for (int i = 0; i < 4; ++i) {
            rs[i] += __shfl_xor_sync(0xffffffffu, rs[i], 1);
            rs[i] += __shfl_xor_sync(0xffffffffu, rs[i], 2);
            llv[i] = llv[i] * al[i] + rs[i];
        }

        // ---- rescale accumulators only when a new row-max appeared ----
        if (__any_sync(0xffffffffu, need_rescale)) {
#pragma unroll
            for (int mt = 0; mt < 2; ++mt)
#pragma unroll
                for (int nt = 0; nt < 8; ++nt) {
                    acc[mt][nt][0] *= al[mt * 2];     acc[mt][nt][1] *= al[mt * 2];
                    acc[mt][nt][2] *= al[mt * 2 + 1]; acc[mt][nt][3] *= al[mt * 2 + 1];
                }
        }

        // ---- O += P V: B-frags via ldmatrix.trans from row-major V ----
        const uint32_t Vd_u = Vs_u + (uint32_t)(db * FKS_B) + bv_lane;
#pragma unroll
        for (int ks = 0; ks < 2; ++ks) {
            const uint32_t vtok_off =
                (uint32_t)(wc * 32 + ks * 16) * KSTRB;
#pragma unroll
            for (int ntp = 0; ntp < 4; ++ntp) {
                uint32_t b[4];
                ldsm4t(b, Vd_u + vtok_off + (uint32_t)(ntp * 16) * 2);
#pragma unroll
                for (int mt = 0; mt < 2; ++mt) {
                    mma16(acc[mt][ntp * 2],     pa[mt][ks], b);
                    mma16(acc[mt][ntp * 2 + 1], pa[mt][ks], b + 2);
                }
            }
        }
    }

    // ---- epilogue: 2-way split-KV combine across the two column groups ----
    if (ls == 0) {
#pragma unroll
        for (int mt = 0; mt < 2; ++mt) {
            const int r = row0 + mt * 16 + lq;
            cm[wc * 128 + r]     = mm[mt * 2];
            cm[wc * 128 + r + 8] = mm[mt * 2 + 1];
            cl[wc * 128 + r]     = llv[mt * 2];
            cl[wc * 128 + r + 8] = llv[mt * 2 + 1];
        }
    }
    __syncthreads();                     // also fences all loop smem reads

    float sS[4], lt[4];
#pragma unroll
    for (int i = 0; i < 4; ++i) {
        const int row = row0 + (i >> 1) * 16 + (i & 1) * 8 + lq;
        const float mo = cm[(wc ^ 1) * 128 + row];
        const float lo = cl[(wc ^ 1) * 128 + row];
        const float M  = fmaxf(mm[i], mo);
        sS[i] = __expf(mm[i] - M);
        lt[i] = llv[i] * sS[i] + lo * __expf(mo - M);
    }

    if (wc == 1) {                       // publish scaled partial O
#pragma unroll
        for (int mt = 0; mt < 2; ++mt) {
            const int r = row0 + mt * 16 + lq;
#pragma unroll
            for (int nt = 0; nt < 8; ++nt) {
                const int cc = nt * 8 + ls * 2;
                float2 w0, w1;
                w0.x = acc[mt][nt][0] * sS[mt * 2];
                w0.y = acc[mt][nt][1] * sS[mt * 2];
                w1.x = acc[mt][nt][2] * sS[mt * 2 + 1];
                w1.y = acc[mt][nt][3] * sS[mt * 2 + 1];
                *(float2*)(ac + r * 66 + cc)       = w0;
                *(float2*)(ac + (r + 8) * 66 + cc) = w1;
            }
        }
    }
    __syncthreads();

    if (wc == 0) {
        const int b = bh >> 4;
        const int h = bh & 15;
#pragma unroll
        for (int mt = 0; mt < 2; ++mt) {
            const float inv0 = 1.f / lt[mt * 2];
            const float inv1 = 1.f / lt[mt * 2 + 1];
            const int r  = row0 + mt * 16 + lq;
            const int rg = qi * 128 + r;
#pragma unroll
            for (int nt = 0; nt < 8; ++nt) {
                const int cc = nt * 8 + ls * 2;
                const float2 p0 = *(const float2*)(ac + r * 66 + cc);
                const float2 p1 = *(const float2*)(ac + (r + 8) * 66 + cc);
                const int cn = h * HD + cc;
                const uint32_t o0 = pack_h2(
                    (acc[mt][nt][0] * sS[mt * 2] + p0.x) * inv0,
                    (acc[mt][nt][1] * sS[mt * 2] + p0.y) * inv0);
                const uint32_t o1 = pack_h2(
                    (acc[mt][nt][2] * sS[mt * 2 + 1] + p1.x) * inv1,
                    (acc[mt][nt][3] * sS[mt * 2 + 1] + p1.y) * inv1);
                *(uint32_t*)(ctx + (size_t)(b * LL + rg) * DD + cn)     = o0;
                *(uint32_t*)(ctx + (size_t)(b * LL + rg + 8) * DD + cn) = o1;
            }
        }
    }
}

// ---------------------------------------------------------------------------
// Launch
// ---------------------------------------------------------------------------
extern "C" void kernel_launch(void* const* d_in, const int* in_sizes, int n_in,
                              void* d_out, int out_size)
{
    const float* x       = (const float*)d_in[0];
    const float* Wqkv_w  = (const float*)d_in[2];
    const float* Wqkv_b  = (const float*)d_in[3];
    const float* Wout_w  = (const float*)d_in[4];
    const float* Wout_b  = (const float*)d_in[5];

    float* out  = (float*)d_out;
    float* kout = out + BLD;
    float* vout = kout + BLD;

    __half *xr, *wqkv, *wout_r, *qh, *kh, *vh, *ctx;
    float  *qkv;
    cudaGetSymbolAddress((void**)&xr,     g_xr);
    cudaGetSymbolAddress((void**)&wqkv,   g_wqkv);
    cudaGetSymbolAddress((void**)&wout_r, g_wout);
    cudaGetSymbolAddress((void**)&qkv,    g_qkv);
    cudaGetSymbolAddress((void**)&qh,     g_q);
    cudaGetSymbolAddress((void**)&kh,     g_k);
    cudaGetSymbolAddress((void**)&vh,     g_v);
    cudaGetSymbolAddress((void**)&ctx,    g_ctx);

    cudaFuncSetAttribute(gemm_mma,
                         cudaFuncAttributeMaxDynamicSharedMemorySize, GEMM_SMEM);
    cudaFuncSetAttribute(flash_mma,
                         cudaFuncAttributeMaxDynamicSharedMemorySize, FLASH_SMEM);

    round_all<<<(RND_TOTAL4 + 255) / 256, 256>>>(
        (const float4*)x, xr,
        (const float4*)Wqkv_w, wqkv,
        (const float4*)Wout_w, wout_r);

    gemm_mma<<<dim3(QKV_N / 128, ROWS / 128), 256, GEMM_SMEM>>>(
        xr, wqkv, Wqkv_b, qkv, QKV_N, DD);

    rope_scatter<<<(BB * LL * HH * 32) / 256, 256>>>(qkv, qh, kh, vh, kout, vout);

    flash_mma<<<dim3(LL / 128, BB * HH), 256, FLASH_SMEM>>>(qh, kh, vh, ctx);

    gemm_mma<<<dim3(DD / 128, ROWS / 128), 256, GEMM_SMEM>>>(
        ctx, wout_r, Wout_b, out, DD, DD);
}

// round 15
// speedup vs baseline: 1.0143x; 1.0143x over previous
#include <cuda_runtime.h>
#include <cuda_fp16.h>
#include <cstdint>

// Problem shape constants (fixed by the reference).
#define BB 2
#define LL 2048
#define DD 1024
#define HH 16
#define HD 64
#define ROWS (BB*LL)            // 4096
#define QKV_N (3*DD)            // 3072
#define BLD (BB*LL*DD)          // 4194304
#define WQKV_SZ (QKV_N*DD)      // 3145728
#define WOUT_SZ (DD*DD)         // 1048576

// ---------------------------------------------------------------------------
// Scratch (alloc-free rule: __device__ globals)
// ---------------------------------------------------------------------------
__device__ __half g_xr  [BLD];            // x -> fp16
__device__ __half g_wqkv[WQKV_SZ];        // Wqkv -> fp16
__device__ __half g_wout[WOUT_SZ];        // Wout -> fp16
__device__ __half g_qkvh[ROWS * QKV_N];   // qkv projection (fp16)
__device__ __half g_q   [BLD];            // q heads, rope'd, scaled, fp16
__device__ __half g_k   [BLD];            // k heads, rope'd, fp16
__device__ __half g_v   [BLD];            // v heads, fp16
__device__ __half g_ctx [BLD];            // attention context, fp16

// ---------------------------------------------------------------------------
// Helpers
// ---------------------------------------------------------------------------
__device__ __forceinline__ uint32_t smem_u32(const void* p) {
    uint32_t a;
    asm("{ .reg .u64 t; cvta.to.shared.u64 t, %1; cvt.u32.u64 %0, t; }"
        : "=r"(a) : "l"(p));
    return a;
}

// m16n8k16 fp16 mma, fp32 accumulate (.row.col)
__device__ __forceinline__ void mma16(float* c, const uint32_t* a, const uint32_t* b) {
    asm volatile(
        "mma.sync.aligned.m16n8k16.row.col.f32.f16.f16.f32 "
        "{%0,%1,%2,%3}, {%4,%5,%6,%7}, {%8,%9}, {%0,%1,%2,%3};"
        : "+f"(c[0]), "+f"(c[1]), "+f"(c[2]), "+f"(c[3])
        : "r"(a[0]), "r"(a[1]), "r"(a[2]), "r"(a[3]), "r"(b[0]), "r"(b[1]));
}

// ldmatrix x4 b16
__device__ __forceinline__ void ldsm4(uint32_t* r, uint32_t addr) {
    asm volatile(
        "ldmatrix.sync.aligned.m8n8.x4.shared.b16 {%0,%1,%2,%3}, [%4];"
        : "=r"(r[0]), "=r"(r[1]), "=r"(r[2]), "=r"(r[3]) : "r"(addr));
}

// ldmatrix x4 b16 transposed (for V: row-major smem -> col-major fragment)
__device__ __forceinline__ void ldsm4t(uint32_t* r, uint32_t addr) {
    asm volatile(
        "ldmatrix.sync.aligned.m8n8.x4.trans.shared.b16 {%0,%1,%2,%3}, [%4];"
        : "=r"(r[0]), "=r"(r[1]), "=r"(r[2]), "=r"(r[3]) : "r"(addr));
}

__device__ __forceinline__ uint32_t pack_h2(float a, float b) {
    __half2 h = __floats2half2_rn(a, b);
    return *(uint32_t*)&h;
}

#define CP16(dst, src) \
    asm volatile("cp.async.cg.shared.global [%0], [%1], 16;" :: "r"(dst), "l"(src))
#define CP_COMMIT() asm volatile("cp.async.commit_group;" ::: "memory")
#define CP_WAIT(n)  asm volatile("cp.async.wait_group %0;" :: "n"(n) : "memory")

// ---------------------------------------------------------------------------
// Fused fp32 -> fp16 conversion of x, Wqkv, Wout
// ---------------------------------------------------------------------------
#define RND_TOTAL4 ((BLD + WQKV_SZ + WOUT_SZ) / 4)

__global__ __launch_bounds__(256) void round_all(
    const float4* __restrict__ x,   __half* __restrict__ xr,
    const float4* __restrict__ wq,  __half* __restrict__ wqr,
    const float4* __restrict__ wo,  __half* __restrict__ wor)
{
    int i = blockIdx.x * 256 + threadIdx.x;
    if (i >= RND_TOTAL4) return;
    const float4* src; __half* dst;
    if (i < BLD/4)                       { src = x;  dst = xr;  }
    else if (i < (BLD + WQKV_SZ)/4)      { src = wq; dst = wqr; i -= BLD/4; }
    else                                 { src = wo; dst = wor; i -= (BLD + WQKV_SZ)/4; }
    float4 v = src[i];
    uint2 o;
    o.x = pack_h2(v.x, v.y);
    o.y = pack_h2(v.z, v.w);
    *(uint2*)(dst + (size_t)i * 4) = o;
}

// ---------------------------------------------------------------------------
// fp16 mma.sync NT GEMM, 3-stage cp.async pipeline, templated output type.
// 128x128 CTA tile, BK=32 halves, 256 threads (8 warps, 2x4 of 64x32 tiles).
// smem rows padded to 40 halves (80B = 5*16B -> ldmatrix conflict-free).
// ---------------------------------------------------------------------------
#define HSTR 40
#define GEMM_TILE_B (128 * HSTR * 2)          // 10240 B per matrix per stage
#define GEMM_STAGES 3
#define GEMM_SMEM   (2 * GEMM_STAGES * GEMM_TILE_B)   // 61440 B

template<typename OutT>
__global__ __launch_bounds__(256) void gemm_mma(
    const __half* __restrict__ A, const __half* __restrict__ B,
    const float* __restrict__ bias, OutT* __restrict__ C,
    int N, int K)
{
    extern __shared__ char smraw[];
    const uint32_t As_u = smem_u32(smraw);
    const uint32_t Bs_u = As_u + GEMM_STAGES * GEMM_TILE_B;

    const int tid  = threadIdx.x;
    const int lane = tid & 31;
    const int wid  = tid >> 5;
    const int wm   = wid & 1;
    const int wn   = wid >> 1;
    const int lq   = lane >> 2;
    const int ls   = lane & 3;
    const int s    = lane >> 3;
    const int srow = lane & 7;

    const uint32_t a_lane =
        (uint32_t)(wm * 64 + (s & 1) * 8 + srow) * (HSTR * 2) + (s >> 1) * 16;
    const uint32_t b_lane =
        (uint32_t)(wn * 32 + (s >> 1) * 8 + srow) * (HSTR * 2) + (s & 1) * 16;

    const __half* Ab = A + (size_t)(blockIdx.y * 128) * K;
    const __half* Bb = B + (size_t)(blockIdx.x * 128) * K;
    const int KS = K >> 5;

    float acc[4][4][4];
#pragma unroll
    for (int mt = 0; mt < 4; ++mt)
#pragma unroll
        for (int nt = 0; nt < 4; ++nt)
#pragma unroll
            for (int r = 0; r < 4; ++r) acc[mt][nt][r] = 0.f;

#define GEMM_LOAD(ks, stg)                                                    \
    {                                                                         \
        const int k0 = (ks) * 32;                                             \
        const uint32_t dA = As_u + (stg) * GEMM_TILE_B;                       \
        const uint32_t dB = Bs_u + (stg) * GEMM_TILE_B;                       \
        _Pragma("unroll")                                                     \
        for (int i = 0; i < 2; ++i) {                                         \
            const int c   = tid + i * 256;                                    \
            const int row = c >> 2;                                           \
            const int cc  = (c & 3) * 8;                                      \
            const uint32_t off = (uint32_t)row * (HSTR * 2) + cc * 2;         \
            CP16(dA + off, Ab + (size_t)row * K + k0 + cc);                   \
            CP16(dB + off, Bb + (size_t)row * K + k0 + cc);                   \
        }                                                                     \
        CP_COMMIT();                                                          \
    }

    GEMM_LOAD(0, 0);
    GEMM_LOAD(1, 1);

    int db = 0, nb = 2;
    for (int ks = 0; ks < KS; ++ks) {
        CP_WAIT(1);                      // stage ks arrived (<=1 in flight)
        __syncthreads();                 // all warps done with stage (ks-1)

        if (ks + 2 < KS) {
            GEMM_LOAD(ks + 2, nb);
            nb = (nb + 1 == GEMM_STAGES) ? 0 : nb + 1;
        }

        const uint32_t Ad_u = As_u + db * GEMM_TILE_B;
        const uint32_t Bd_u = Bs_u + db * GEMM_TILE_B;

#pragma unroll
        for (int kk = 0; kk < 2; ++kk) {
            uint32_t a[4][4], b[2][4];
#pragma unroll
            for (int mt = 0; mt < 4; ++mt)
                ldsm4(a[mt], Ad_u + a_lane +
                      (uint32_t)(mt * 16 * HSTR * 2 + kk * 32));
#pragma unroll
            for (int ntp = 0; ntp < 2; ++ntp)
                ldsm4(b[ntp], Bd_u + b_lane +
                      (uint32_t)(ntp * 16 * HSTR * 2 + kk * 32));
#pragma unroll
            for (int mt = 0; mt < 4; ++mt)
#pragma unroll
                for (int nt = 0; nt < 4; ++nt)
                    mma16(acc[mt][nt], a[mt], &b[nt >> 1][(nt & 1) * 2]);
        }
        db = (db + 1 == GEMM_STAGES) ? 0 : db + 1;
    }

    const int row_base = blockIdx.y * 128 + wm * 64;
    const int col_base = blockIdx.x * 128 + wn * 32;
#pragma unroll
    for (int mt = 0; mt < 4; ++mt) {
        const int r0 = row_base + mt * 16 + lq;
#pragma unroll
        for (int nt = 0; nt < 4; ++nt) {
            const int cn = col_base + nt * 8 + ls * 2;
            const float2 bb = *(const float2*)(bias + cn);
            const float v00 = acc[mt][nt][0] + bb.x;
            const float v01 = acc[mt][nt][1] + bb.y;
            const float v10 = acc[mt][nt][2] + bb.x;
            const float v11 = acc[mt][nt][3] + bb.y;
            if constexpr (sizeof(OutT) == 2) {
                *(uint32_t*)((__half*)C + (size_t)r0 * N + cn)       = pack_h2(v00, v01);
                *(uint32_t*)((__half*)C + (size_t)(r0 + 8) * N + cn) = pack_h2(v10, v11);
            } else {
                float2 o0, o1;
                o0.x = v00; o0.y = v01; o1.x = v10; o1.y = v11;
                *(float2*)((float*)C + (size_t)r0 * N + cn)       = o0;
                *(float2*)((float*)C + (size_t)(r0 + 8) * N + cn) = o1;
            }
        }
    }
}

// ---------------------------------------------------------------------------
// RoPE + head scatter, reading fp16 qkv.
// k,v outputs (fp32, d_out) carry one fp16 rounding from the qkv store.
// ---------------------------------------------------------------------------
__global__ __launch_bounds__(256) void rope_scatter(
    const __half* __restrict__ qkv,
    __half* __restrict__ qh, __half* __restrict__ kh, __half* __restrict__ vh,
    float* __restrict__ kout, float* __restrict__ vout)
{
    const int t = blockIdx.x * blockDim.x + threadIdx.x;
    const int d = t & 31;
    const int h = (t >> 5) & 15;
    const int l = (t >> 9) & 2047;
    const int b = t >> 20;

    const __half* base = qkv + (size_t)(b * LL + l) * QKV_N;

    const float inv = __expf(-(float)d * (9.210340371976184f / 32.f));
    const float ang = (float)l * inv;
    float sn, cs;
    sincosf(ang, &sn, &cs);

    const size_t ob = ((size_t)((b * HH + h) * LL + l)) * HD;

    const float q1 = __half2float(base[h*HD + d]);
    const float q2 = __half2float(base[h*HD + d + 32]);
    qh[ob + d]      = __float2half_rn((q1 * cs - q2 * sn) * 0.125f);
    qh[ob + d + 32] = __float2half_rn((q1 * sn + q2 * cs) * 0.125f);

    const float k1 = __half2float(base[DD + h*HD + d]);
    const float k2 = __half2float(base[DD + h*HD + d + 32]);
    const float kr1 = k1 * cs - k2 * sn;
    const float kr2 = k1 * sn + k2 * cs;
    kout[ob + d]      = kr1;
    kout[ob + d + 32] = kr2;
    kh[ob + d]        = __float2half_rn(kr1);
    kh[ob + d + 32]   = __float2half_rn(kr2);

    const __half v1 = base[2*DD + h*HD + d];
    const __half v2 = base[2*DD + h*HD + d + 32];
    vout[ob + d]      = __half2float(v1);
    vout[ob + d + 32] = __half2float(v2);
    vh[ob + d]        = v1;
    vh[ob + d + 32]   = v2;
}

// ---------------------------------------------------------------------------
// Flash attention v10 (fp16, register-P, ldmatrix.trans V) -- R13 state
// (lazy rescale reverted). Br=128, Bc=64, 256 threads (8 warps = 4r x 2c).
// smem bytes: Ks[2][64*72h] | Vs[2][64*72h] | cm[2][128]f | cl[2][128]f.
// Epilogue 'ac' (128 x 66 fp32) aliases Ks+Vs (dead by then).
// ---------------------------------------------------------------------------
#define KSTRB 144                     // 72 halves per row
#define FKS_B  (64 * KSTRB)           // 9216 per K/V buffer
#define FVT_O  (2 * FKS_B)            // 18432
#define FCM_O  (FVT_O + 2 * FKS_B)    // 36864
#define FCL_O  (FCM_O + 1024)         // 37888
#define FLASH_SMEM (FCL_O + 1024)     // 38912 B

__global__ __launch_bounds__(256) void flash_mma(
    const __half* __restrict__ Q, const __half* __restrict__ K,
    const __half* __restrict__ V, __half* __restrict__ ctx)
{
    extern __shared__ char smraw[];
    float*  cm = (float*)(smraw + FCM_O);   // [2][128]
    float*  cl = (float*)(smraw + FCL_O);   // [2][128]
    float*  ac = (float*)smraw;             // epilogue alias, stride 66
    const uint32_t Ks_u = smem_u32(smraw);
    const uint32_t Vs_u = Ks_u + FVT_O;

    const int qi   = gridDim.x - 1 - blockIdx.x;   // heavy tiles first
    const int bh   = blockIdx.y;
    const int tid  = threadIdx.x;
    const int lane = tid & 31;
    const int wid  = tid >> 5;           // 0..7
    const int wr   = wid & 3;            // row group (4 x 32 rows)
    const int wc   = wid >> 2;           // col group (2 x 32 tokens)
    const int lq   = lane >> 2;
    const int ls   = lane & 3;
    const int s    = lane >> 3;
    const int srow = lane & 7;
    const int row0 = wr * 32;

    const uint32_t bk_lane =
        (uint32_t)((s >> 1) * 8 + srow) * KSTRB + (s & 1) * 16;
    const uint32_t bv_lane =
        (uint32_t)((s & 1) * 8 + srow) * KSTRB + (s >> 1) * 16;

    const __half* Qb = Q + ((size_t)bh * LL + qi * 128) * HD;
    const __half* Kb = K + (size_t)bh * LL * HD;
    const __half* Vb = V + (size_t)bh * LL * HD;

#define FL_LOAD_T(dst_u, src)                                                 \
    {                                                                         \
        _Pragma("unroll")                                                     \
        for (int i = 0; i < 2; ++i) {                                         \
            const int c   = tid + i * 256;                                    \
            const int row = c >> 3;                                           \
            const int cc  = (c & 7) * 8;                                      \
            CP16((dst_u) + (uint32_t)row * KSTRB + cc * 2,                    \
                 (src) + (size_t)row * HD + cc);                              \
        }                                                                     \
    }

    FL_LOAD_T(Ks_u, Kb);
    FL_LOAD_T(Vs_u, Vb);
    CP_COMMIT();

    uint32_t qf[4][2][4];
#pragma unroll
    for (int ks = 0; ks < 4; ++ks) {
#pragma unroll
        for (int mt = 0; mt < 2; ++mt) {
            const int r = row0 + mt * 16 + lq;
            const __half* q0 = Qb + (size_t)r * HD + ks * 16;
            const __half* q1 = Qb + (size_t)(r + 8) * HD + ks * 16;
            qf[ks][mt][0] = *(const uint32_t*)(q0 + 2 * ls);
            qf[ks][mt][1] = *(const uint32_t*)(q1 + 2 * ls);
            qf[ks][mt][2] = *(const uint32_t*)(q0 + 8 + 2 * ls);
            qf[ks][mt][3] = *(const uint32_t*)(q1 + 8 + 2 * ls);
        }
    }

    float acc[2][8][4];
#pragma unroll
    for (int mt = 0; mt < 2; ++mt)
#pragma unroll
        for (int nt = 0; nt < 8; ++nt)
#pragma unroll
            for (int r = 0; r < 4; ++r) acc[mt][nt][r] = 0.f;
    float mm[4] = {-1e30f, -1e30f, -1e30f, -1e30f};
    float llv[4] = {0.f, 0.f, 0.f, 0.f};

    const int jtmax = 2 * qi + 1;

    for (int jt = 0; jt <= jtmax; ++jt) {
        const int db = jt & 1;
        CP_WAIT(0);
        __syncthreads();

        if (jt < jtmax) {
            FL_LOAD_T(Ks_u + (uint32_t)((db ^ 1) * FKS_B),
                      Kb + (size_t)(jt + 1) * 64 * HD);
            FL_LOAD_T(Vs_u + (uint32_t)((db ^ 1) * FKS_B),
                      Vb + (size_t)(jt + 1) * 64 * HD);
            CP_COMMIT();
        }

        // ---- S = Q K^T ----
        float sc[2][4][4];
#pragma unroll
        for (int mt = 0; mt < 2; ++mt)
#pragma unroll
            for (int nt = 0; nt < 4; ++nt)
#pragma unroll
                for (int r = 0; r < 4; ++r) sc[mt][nt][r] = 0.f;

        const uint32_t Kd_u = Ks_u + (uint32_t)(db * FKS_B)
                            + (uint32_t)(wc * 32) * KSTRB + bk_lane;
#pragma unroll
        for (int ks = 0; ks < 4; ++ks) {
#pragma unroll
            for (int ntp = 0; ntp < 2; ++ntp) {
                uint32_t b[4];
                ldsm4(b, Kd_u + (uint32_t)(ntp * 16) * KSTRB + ks * 32);
#pragma unroll
                for (int mt = 0; mt < 2; ++mt) {
                    mma16(sc[mt][ntp * 2],     qf[ks][mt], b);
                    mma16(sc[mt][ntp * 2 + 1], qf[ks][mt], b + 2);
                }
            }
        }

        // ---- causal mask (last two tiles) ----
        if (jt >= 2 * qi) {
            const int cbase = jt * 64 + wc * 32;
#pragma unroll
            for (int mt = 0; mt < 2; ++mt) {
                const int rg0 = qi * 128 + row0 + mt * 16 + lq;
#pragma unroll
                for (int nt = 0; nt < 4; ++nt) {
                    const int cg = cbase + nt * 8 + ls * 2;
                    if (cg > rg0)         sc[mt][nt][0] += -1000000000.0f;
                    if (cg + 1 > rg0)     sc[mt][nt][1] += -1000000000.0f;
                    if (cg > rg0 + 8)     sc[mt][nt][2] += -1000000000.0f;
                    if (cg + 1 > rg0 + 8) sc[mt][nt][3] += -1000000000.0f;
                }
            }
        }

        // ---- row max per row-pair group (quad shfl) ----
        float mx[4];
#pragma unroll
        for (int mt = 0; mt < 2; ++mt) {
            float a0 = sc[mt][0][0], a1 = sc[mt][0][2];
#pragma unroll
            for (int nt = 0; nt < 4; ++nt) {
                a0 = fmaxf(a0, fmaxf(sc[mt][nt][0], sc[mt][nt][1]));
                a1 = fmaxf(a1, fmaxf(sc[mt][nt][2], sc[mt][nt][3]));
            }
            mx[mt * 2]     = a0;
            mx[mt * 2 + 1] = a1;
        }
#pragma unroll
        for (int i = 0; i < 4; ++i) {
            mx[i] = fmaxf(mx[i], __shfl_xor_sync(0xffffffffu, mx[i], 1));
            mx[i] = fmaxf(mx[i], __shfl_xor_sync(0xffffffffu, mx[i], 2));
        }

        float al[4];
#pragma unroll
        for (int i = 0; i < 4; ++i) {
            const float mn = fmaxf(mm[i], mx[i]);
            al[i] = __expf(mm[i] - mn);
            mm[i] = mn;
        }

        // ---- P = exp(S - m): pack straight into PV A-fragments ----
        uint32_t pa[2][2][4];
        float rs[4] = {0.f, 0.f, 0.f, 0.f};
#pragma unroll
        for (int mt = 0; mt < 2; ++mt) {
            const float mn0 = mm[mt * 2], mn1 = mm[mt * 2 + 1];
#pragma unroll
            for (int nt = 0; nt < 4; ++nt) {
                const float p0 = __expf(sc[mt][nt][0] - mn0);
                const float p1 = __expf(sc[mt][nt][1] - mn0);
                const float p2 = __expf(sc[mt][nt][2] - mn1);
                const float p3 = __expf(sc[mt][nt][3] - mn1);
                rs[mt * 2]     += p0 + p1;
                rs[mt * 2 + 1] += p2 + p3;
                pa[mt][nt >> 1][(nt & 1) * 2 + 0] = pack_h2(p0, p1);
                pa[mt][nt >> 1][(nt & 1) * 2 + 1] = pack_h2(p2, p3);
            }
        }
#pragma unroll
        for (int i = 0; i < 4; ++i) {
            rs[i] += __shfl_xor_sync(0xffffffffu, rs[i], 1);
            rs[i] += __shfl_xor_sync(0xffffffffu, rs[i], 2);
            llv[i] = llv[i] * al[i] + rs[i];
        }

#pragma unroll
        for (int mt = 0; mt < 2; ++mt)
#pragma unroll
            for (int nt = 0; nt < 8; ++nt) {
                acc[mt][nt][0] *= al[mt * 2];     acc[mt][nt][1] *= al[mt * 2];
                acc[mt][nt][2] *= al[mt * 2 + 1]; acc[mt][nt][3] *= al[mt * 2 + 1];
            }

        // ---- O += P V: B-frags via ldmatrix.trans from row-major V ----
        const uint32_t Vd_u = Vs_u + (uint32_t)(db * FKS_B) + bv_lane;
#pragma unroll
        for (int ks = 0; ks < 2; ++ks) {
            const uint32_t vtok_off =
                (uint32_t)(wc * 32 + ks * 16) * KSTRB;
#pragma unroll
            for (int ntp = 0; ntp < 4; ++ntp) {
                uint32_t b[4];
                ldsm4t(b, Vd_u + vtok_off + (uint32_t)(ntp * 16) * 2);
#pragma unroll
                for (int mt = 0; mt < 2; ++mt) {
                    mma16(acc[mt][ntp * 2],     pa[mt][ks], b);
                    mma16(acc[mt][ntp * 2 + 1], pa[mt][ks], b + 2);
                }
            }
        }
    }

    // ---- epilogue: 2-way split-KV combine across the two column groups ----
    if (ls == 0) {
#pragma unroll
        for (int mt = 0; mt < 2; ++mt) {
            const int r = row0 + mt * 16 + lq;
            cm[wc * 128 + r]     = mm[mt * 2];
            cm[wc * 128 + r + 8] = mm[mt * 2 + 1];
            cl[wc * 128 + r]     = llv[mt * 2];
            cl[wc * 128 + r + 8] = llv[mt * 2 + 1];
        }
    }
    __syncthreads();

    float sS[4], lt[4];
#pragma unroll
    for (int i = 0; i < 4; ++i) {
        const int row = row0 + (i >> 1) * 16 + (i & 1) * 8 + lq;
        const float mo = cm[(wc ^ 1) * 128 + row];
        const float lo = cl[(wc ^ 1) * 128 + row];
        const float M  = fmaxf(mm[i], mo);
        sS[i] = __expf(mm[i] - M);
        lt[i] = llv[i] * sS[i] + lo * __expf(mo - M);
    }

    if (wc == 1) {
#pragma unroll
        for (int mt = 0; mt < 2; ++mt) {
            const int r = row0 + mt * 16 + lq;
#pragma unroll
            for (int nt = 0; nt < 8; ++nt) {
                const int cc = nt * 8 + ls * 2;
                float2 w0, w1;
                w0.x = acc[mt][nt][0] * sS[mt * 2];
                w0.y = acc[mt][nt][1] * sS[mt * 2];
                w1.x = acc[mt][nt][2] * sS[mt * 2 + 1];
                w1.y = acc[mt][nt][3] * sS[mt * 2 + 1];
                *(float2*)(ac + r * 66 + cc)       = w0;
                *(float2*)(ac + (r + 8) * 66 + cc) = w1;
            }
        }
    }
    __syncthreads();

    if (wc == 0) {
        const int b = bh >> 4;
        const int h = bh & 15;
#pragma unroll
        for (int mt = 0; mt < 2; ++mt) {
            const float inv0 = 1.f / lt[mt * 2];
            const float inv1 = 1.f / lt[mt * 2 + 1];
            const int r  = row0 + mt * 16 + lq;
            const int rg = qi * 128 + r;
#pragma unroll
            for (int nt = 0; nt < 8; ++nt) {
                const int cc = nt * 8 + ls * 2;
                const float2 p0 = *(const float2*)(ac + r * 66 + cc);
                const float2 p1 = *(const float2*)(ac + (r + 8) * 66 + cc);
                const int cn = h * HD + cc;
                const uint32_t o0 = pack_h2(
                    (acc[mt][nt][0] * sS[mt * 2] + p0.x) * inv0,
                    (acc[mt][nt][1] * sS[mt * 2] + p0.y) * inv0);
                const uint32_t o1 = pack_h2(
                    (acc[mt][nt][2] * sS[mt * 2 + 1] + p1.x) * inv1,
                    (acc[mt][nt][3] * sS[mt * 2 + 1] + p1.y) * inv1);
                *(uint32_t*)(ctx + (size_t)(b * LL + rg) * DD + cn)     = o0;
                *(uint32_t*)(ctx + (size_t)(b * LL + rg + 8) * DD + cn) = o1;
            }
        }
    }
}

// ---------------------------------------------------------------------------
// Launch
// ---------------------------------------------------------------------------
extern "C" void kernel_launch(void* const* d_in, const int* in_sizes, int n_in,
                              void* d_out, int out_size)
{
    const float* x       = (const float*)d_in[0];
    const float* Wqkv_w  = (const float*)d_in[2];
    const float* Wqkv_b  = (const float*)d_in[3];
    const float* Wout_w  = (const float*)d_in[4];
    const float* Wout_b  = (const float*)d_in[5];

    float* out  = (float*)d_out;
    float* kout = out + BLD;
    float* vout = kout + BLD;

    __half *xr, *wqkv, *wout_r, *qkvh, *qh, *kh, *vh, *ctx;
    cudaGetSymbolAddress((void**)&xr,     g_xr);
    cudaGetSymbolAddress((void**)&wqkv,   g_wqkv);
    cudaGetSymbolAddress((void**)&wout_r, g_wout);
    cudaGetSymbolAddress((void**)&qkvh,   g_qkvh);
    cudaGetSymbolAddress((void**)&qh,     g_q);
    cudaGetSymbolAddress((void**)&kh,     g_k);
    cudaGetSymbolAddress((void**)&vh,     g_v);
    cudaGetSymbolAddress((void**)&ctx,    g_ctx);

    cudaFuncSetAttribute(gemm_mma<__half>,
                         cudaFuncAttributeMaxDynamicSharedMemorySize, GEMM_SMEM);
    cudaFuncSetAttribute(gemm_mma<float>,
                         cudaFuncAttributeMaxDynamicSharedMemorySize, GEMM_SMEM);
    cudaFuncSetAttribute(flash_mma,
                         cudaFuncAttributeMaxDynamicSharedMemorySize, FLASH_SMEM);

    round_all<<<(RND_TOTAL4 + 255) / 256, 256>>>(
        (const float4*)x, xr,
        (const float4*)Wqkv_w, wqkv,
        (const float4*)Wout_w, wout_r);

    gemm_mma<__half><<<dim3(QKV_N / 128, ROWS / 128), 256, GEMM_SMEM>>>(
        xr, wqkv, Wqkv_b, qkvh, QKV_N, DD);

    rope_scatter<<<(BB * LL * HH * 32) / 256, 256>>>(qkvh, qh, kh, vh, kout, vout);

    flash_mma<<<dim3(LL / 128, BB * HH), 256, FLASH_SMEM>>>(qh, kh, vh, ctx);

    gemm_mma<float><<<dim3(DD / 128, ROWS / 128), 256, GEMM_SMEM>>>(
        ctx, wout_r, Wout_b, out, DD, DD);
}

// round 16
// speedup vs baseline: 1.0502x; 1.0354x over previous
#include <cuda_runtime.h>
#include <cuda_fp16.h>
#include <cstdint>

// Problem shape constants (fixed by the reference).
#define BB 2
#define LL 2048
#define DD 1024
#define HH 16
#define HD 64
#define ROWS (BB*LL)            // 4096
#define QKV_N (3*DD)            // 3072
#define BLD (BB*LL*DD)          // 4194304
#define WQKV_SZ (QKV_N*DD)      // 3145728
#define WOUT_SZ (DD*DD)         // 1048576

// ---------------------------------------------------------------------------
// Scratch (alloc-free rule: __device__ globals)
// ---------------------------------------------------------------------------
__device__ __half g_xr  [BLD];            // x -> fp16
__device__ __half g_wqkv[WQKV_SZ];        // Wqkv -> fp16
__device__ __half g_wout[WOUT_SZ];        // Wout -> fp16
__device__ __half g_q   [BLD];            // q heads, rope'd, scaled, fp16
__device__ __half g_k   [BLD];            // k heads, rope'd, fp16
__device__ __half g_v   [BLD];            // v heads, fp16
__device__ __half g_ctx [BLD];            // attention context, fp16

// ---------------------------------------------------------------------------
// Helpers
// ---------------------------------------------------------------------------
__device__ __forceinline__ uint32_t smem_u32(const void* p) {
    uint32_t a;
    asm("{ .reg .u64 t; cvta.to.shared.u64 t, %1; cvt.u32.u64 %0, t; }"
        : "=r"(a) : "l"(p));
    return a;
}

// m16n8k16 fp16 mma, fp32 accumulate (.row.col)
__device__ __forceinline__ void mma16(float* c, const uint32_t* a, const uint32_t* b) {
    asm volatile(
        "mma.sync.aligned.m16n8k16.row.col.f32.f16.f16.f32 "
        "{%0,%1,%2,%3}, {%4,%5,%6,%7}, {%8,%9}, {%0,%1,%2,%3};"
        : "+f"(c[0]), "+f"(c[1]), "+f"(c[2]), "+f"(c[3])
        : "r"(a[0]), "r"(a[1]), "r"(a[2]), "r"(a[3]), "r"(b[0]), "r"(b[1]));
}

// ldmatrix x4 b16
__device__ __forceinline__ void ldsm4(uint32_t* r, uint32_t addr) {
    asm volatile(
        "ldmatrix.sync.aligned.m8n8.x4.shared.b16 {%0,%1,%2,%3}, [%4];"
        : "=r"(r[0]), "=r"(r[1]), "=r"(r[2]), "=r"(r[3]) : "r"(addr));
}

// ldmatrix x4 b16 transposed (for V: row-major smem -> col-major fragment)
__device__ __forceinline__ void ldsm4t(uint32_t* r, uint32_t addr) {
    asm volatile(
        "ldmatrix.sync.aligned.m8n8.x4.trans.shared.b16 {%0,%1,%2,%3}, [%4];"
        : "=r"(r[0]), "=r"(r[1]), "=r"(r[2]), "=r"(r[3]) : "r"(addr));
}

__device__ __forceinline__ uint32_t pack_h2(float a, float b) {
    __half2 h = __floats2half2_rn(a, b);
    return *(uint32_t*)&h;
}

#define CP16(dst, src) \
    asm volatile("cp.async.cg.shared.global [%0], [%1], 16;" :: "r"(dst), "l"(src))
#define CP_COMMIT() asm volatile("cp.async.commit_group;" ::: "memory")
#define CP_WAIT(n)  asm volatile("cp.async.wait_group %0;" :: "n"(n) : "memory")

// ---------------------------------------------------------------------------
// Fused fp32 -> fp16 conversion of x, Wqkv, Wout
// ---------------------------------------------------------------------------
#define RND_TOTAL4 ((BLD + WQKV_SZ + WOUT_SZ) / 4)

__global__ __launch_bounds__(256) void round_all(
    const float4* __restrict__ x,   __half* __restrict__ xr,
    const float4* __restrict__ wq,  __half* __restrict__ wqr,
    const float4* __restrict__ wo,  __half* __restrict__ wor)
{
    int i = blockIdx.x * 256 + threadIdx.x;
    if (i >= RND_TOTAL4) return;
    const float4* src; __half* dst;
    if (i < BLD/4)                       { src = x;  dst = xr;  }
    else if (i < (BLD + WQKV_SZ)/4)      { src = wq; dst = wqr; i -= BLD/4; }
    else                                 { src = wo; dst = wor; i -= (BLD + WQKV_SZ)/4; }
    float4 v = src[i];
    uint2 o;
    o.x = pack_h2(v.x, v.y);
    o.y = pack_h2(v.z, v.w);
    *(uint2*)(dst + (size_t)i * 4) = o;
}

// ---------------------------------------------------------------------------
// GEMM common: 3-stage cp.async pipeline, 128x128 CTA tile, BK=32 halves,
// 256 threads (8 warps, 2x4 of 64x32 warp tiles), smem rows 40 halves.
// ---------------------------------------------------------------------------
#define HSTR 40
#define GEMM_TILE_B (128 * HSTR * 2)          // 10240 B per matrix per stage
#define GEMM_STAGES 3
#define GEMM_PIPE_B (2 * GEMM_STAGES * GEMM_TILE_B)   // 61440 B
#define QKV_STAGE_F 132                                // staging stride, floats
#define QKV_SMEM    (128 * QKV_STAGE_F * 4)            // 67584 B (>= pipe)

#define GEMM_PROLOG_AND_MAINLOOP(KVAL)                                        \
    const uint32_t As_u = smem_u32(smraw);                                    \
    const uint32_t Bs_u = As_u + GEMM_STAGES * GEMM_TILE_B;                   \
    const int tid  = threadIdx.x;                                             \
    const int lane = tid & 31;                                                \
    const int wid  = tid >> 5;                                                \
    const int wm   = wid & 1;                                                 \
    const int wn   = wid >> 1;                                                \
    const int lq   = lane >> 2;                                               \
    const int ls   = lane & 3;                                                \
    const int s    = lane >> 3;                                               \
    const int srow = lane & 7;                                                \
    const uint32_t a_lane =                                                   \
        (uint32_t)(wm * 64 + (s & 1) * 8 + srow) * (HSTR * 2) + (s >> 1) * 16;\
    const uint32_t b_lane =                                                   \
        (uint32_t)(wn * 32 + (s >> 1) * 8 + srow) * (HSTR * 2) + (s & 1) * 16;\
    const __half* Ab = A + (size_t)(blockIdx.y * 128) * (KVAL);               \
    const __half* Bb = B + (size_t)(blockIdx.x * 128) * (KVAL);               \
    const int KS = (KVAL) >> 5;                                               \
    float acc[4][4][4];                                                       \
    _Pragma("unroll")                                                         \
    for (int mt = 0; mt < 4; ++mt)                                            \
        _Pragma("unroll")                                                     \
        for (int nt = 0; nt < 4; ++nt)                                        \
            _Pragma("unroll")                                                 \
            for (int r = 0; r < 4; ++r) acc[mt][nt][r] = 0.f;                 \
    GEMM_LOAD(0, 0, KVAL);                                                    \
    GEMM_LOAD(1, 1, KVAL);                                                    \
    int db = 0, nb = 2;                                                       \
    for (int ks = 0; ks < KS; ++ks) {                                         \
        CP_WAIT(1);                                                           \
        __syncthreads();                                                      \
        if (ks + 2 < KS) {                                                    \
            GEMM_LOAD(ks + 2, nb, KVAL);                                      \
            nb = (nb + 1 == GEMM_STAGES) ? 0 : nb + 1;                        \
        }                                                                     \
        const uint32_t Ad_u = As_u + db * GEMM_TILE_B;                        \
        const uint32_t Bd_u = Bs_u + db * GEMM_TILE_B;                        \
        _Pragma("unroll")                                                     \
        for (int kk = 0; kk < 2; ++kk) {                                      \
            uint32_t a[4][4], b[2][4];                                        \
            _Pragma("unroll")                                                 \
            for (int mt = 0; mt < 4; ++mt)                                    \
                ldsm4(a[mt], Ad_u + a_lane +                                  \
                      (uint32_t)(mt * 16 * HSTR * 2 + kk * 32));              \
            _Pragma("unroll")                                                 \
            for (int ntp = 0; ntp < 2; ++ntp)                                 \
                ldsm4(b[ntp], Bd_u + b_lane +                                 \
                      (uint32_t)(ntp * 16 * HSTR * 2 + kk * 32));             \
            _Pragma("unroll")                                                 \
            for (int mt = 0; mt < 4; ++mt)                                    \
                _Pragma("unroll")                                             \
                for (int nt = 0; nt < 4; ++nt)                                \
                    mma16(acc[mt][nt], a[mt], &b[nt >> 1][(nt & 1) * 2]);     \
        }                                                                     \
        db = (db + 1 == GEMM_STAGES) ? 0 : db + 1;                            \
    }

#define GEMM_LOAD(ks, stg, KVAL)                                              \
    {                                                                         \
        const int k0 = (ks) * 32;                                             \
        const uint32_t dA = As_u + (stg) * GEMM_TILE_B;                       \
        const uint32_t dB = Bs_u + (stg) * GEMM_TILE_B;                       \
        _Pragma("unroll")                                                     \
        for (int i = 0; i < 2; ++i) {                                         \
            const int c   = tid + i * 256;                                    \
            const int row = c >> 2;                                           \
            const int cc  = (c & 3) * 8;                                      \
            const uint32_t off = (uint32_t)row * (HSTR * 2) + cc * 2;         \
            CP16(dA + off, Ab + (size_t)row * (KVAL) + k0 + cc);              \
            CP16(dB + off, Bb + (size_t)row * (KVAL) + k0 + cc);              \
        }                                                                     \
        CP_COMMIT();                                                          \
    }

// ---------------------------------------------------------------------------
// QKV GEMM with fused RoPE + head scatter epilogue.
// blockIdx.x: 0-7 = q tiles, 8-15 = k tiles, 16-23 = v tiles.
// Epilogue: stage fp32 C tile to smem, rope pairs (d, d+32), scatter to
// g_q/g_k/g_v (fp16) and kout/vout (fp32, exact from accumulator).
// ---------------------------------------------------------------------------
__global__ __launch_bounds__(256) void gemm_qkv_rope(
    const __half* __restrict__ A, const __half* __restrict__ B,
    const float* __restrict__ bias,
    __half* __restrict__ qh, __half* __restrict__ kh, __half* __restrict__ vh,
    float* __restrict__ kout, float* __restrict__ vout)
{
    extern __shared__ char smraw[];
    GEMM_PROLOG_AND_MAINLOOP(DD)

    // ---- stage C tile (with bias) to smem fp32 ----
    __syncthreads();                     // all warps done reading pipe smem
    float* st = (float*)smraw;           // [128][QKV_STAGE_F]
    const int col_base = wn * 32;
#pragma unroll
    for (int mt = 0; mt < 4; ++mt) {
        const int r0 = wm * 64 + mt * 16 + lq;
#pragma unroll
        for (int nt = 0; nt < 4; ++nt) {
            const int cn = col_base + nt * 8 + ls * 2;
            const float2 bb = *(const float2*)(bias + blockIdx.x * 128 + cn);
            float2 o0, o1;
            o0.x = acc[mt][nt][0] + bb.x;  o0.y = acc[mt][nt][1] + bb.y;
            o1.x = acc[mt][nt][2] + bb.x;  o1.y = acc[mt][nt][3] + bb.y;
            *(float2*)(st + r0 * QKV_STAGE_F + cn)       = o0;
            *(float2*)(st + (r0 + 8) * QKV_STAGE_F + cn) = o1;
        }
    }
    __syncthreads();

    // ---- rope + scatter ----
    const int sec = blockIdx.x >> 3;             // 0=q, 1=k, 2=v
    const int hb  = (blockIdx.x & 7) * 2;        // first head in tile
#pragma unroll
    for (int i = 0; i < 8; ++i) {
        const int pg  = tid + i * 256;
        const int row = pg >> 4;
        const int rem = pg & 15;
        const int hh  = rem >> 3;
        const int d4  = (rem & 7) * 4;
        const int h   = hb + hh;
        const int grow = blockIdx.y * 128 + row;
        const int b = grow >> 11, l = grow & 2047;
        const float* p1 = st + row * QKV_STAGE_F + hh * 64 + d4;
        const float4 v1 = *(const float4*)p1;
        const float4 v2 = *(const float4*)(p1 + 32);
        const size_t ob = ((size_t)((b * HH + h) * LL + l)) * HD;

        if (sec == 2) {                          // v: no rotation
            uint2 o1, o2;
            o1.x = pack_h2(v1.x, v1.y); o1.y = pack_h2(v1.z, v1.w);
            o2.x = pack_h2(v2.x, v2.y); o2.y = pack_h2(v2.z, v2.w);
            *(uint2*)(vh + ob + d4)      = o1;
            *(uint2*)(vh + ob + d4 + 32) = o2;
            *(float4*)(vout + ob + d4)      = v1;
            *(float4*)(vout + ob + d4 + 32) = v2;
        } else {
            const float* a1 = &v1.x;
            const float* a2 = &v2.x;
            float r1[4], r2[4];
#pragma unroll
            for (int j = 0; j < 4; ++j) {
                const int d = d4 + j;
                const float inv = __expf(-(float)d * (9.210340371976184f / 32.f));
                float sn, cs;
                sincosf((float)l * inv, &sn, &cs);
                r1[j] = a1[j] * cs - a2[j] * sn;
                r2[j] = a1[j] * sn + a2[j] * cs;
            }
            if (sec == 0) {                      // q: scale + fp16
                uint2 o1, o2;
                o1.x = pack_h2(r1[0] * 0.125f, r1[1] * 0.125f);
                o1.y = pack_h2(r1[2] * 0.125f, r1[3] * 0.125f);
                o2.x = pack_h2(r2[0] * 0.125f, r2[1] * 0.125f);
                o2.y = pack_h2(r2[2] * 0.125f, r2[3] * 0.125f);
                *(uint2*)(qh + ob + d4)      = o1;
                *(uint2*)(qh + ob + d4 + 32) = o2;
            } else {                             // k: fp16 + exact fp32 out
                uint2 o1, o2;
                o1.x = pack_h2(r1[0], r1[1]); o1.y = pack_h2(r1[2], r1[3]);
                o2.x = pack_h2(r2[0], r2[1]); o2.y = pack_h2(r2[2], r2[3]);
                *(uint2*)(kh + ob + d4)      = o1;
                *(uint2*)(kh + ob + d4 + 32) = o2;
                float4 f1, f2;
                f1.x = r1[0]; f1.y = r1[1]; f1.z = r1[2]; f1.w = r1[3];
                f2.x = r2[0]; f2.y = r2[1]; f2.z = r2[2]; f2.w = r2[3];
                *(float4*)(kout + ob + d4)      = f1;
                *(float4*)(kout + ob + d4 + 32) = f2;
            }
        }
    }
}

// ---------------------------------------------------------------------------
// Output-projection GEMM (fp32 out), same mainloop.
// ---------------------------------------------------------------------------
__global__ __launch_bounds__(256) void gemm_out(
    const __half* __restrict__ A, const __half* __restrict__ B,
    const float* __restrict__ bias, float* __restrict__ C, int N)
{
    extern __shared__ char smraw[];
    GEMM_PROLOG_AND_MAINLOOP(DD)

    const int row_base = blockIdx.y * 128 + wm * 64;
    const int col_base2 = blockIdx.x * 128 + wn * 32;
#pragma unroll
    for (int mt = 0; mt < 4; ++mt) {
        const int r0 = row_base + mt * 16 + lq;
#pragma unroll
        for (int nt = 0; nt < 4; ++nt) {
            const int cn = col_base2 + nt * 8 + ls * 2;
            const float2 bb = *(const float2*)(bias + cn);
            float2 o0, o1;
            o0.x = acc[mt][nt][0] + bb.x;  o0.y = acc[mt][nt][1] + bb.y;
            o1.x = acc[mt][nt][2] + bb.x;  o1.y = acc[mt][nt][3] + bb.y;
            *(float2*)(C + (size_t)r0 * N + cn)       = o0;
            *(float2*)(C + (size_t)(r0 + 8) * N + cn) = o1;
        }
    }
}

// ---------------------------------------------------------------------------
// Flash attention v10 (fp16, register-P, ldmatrix.trans V) -- unchanged.
// ---------------------------------------------------------------------------
#define KSTRB 144                     // 72 halves per row
#define FKS_B  (64 * KSTRB)           // 9216 per K/V buffer
#define FVT_O  (2 * FKS_B)            // 18432
#define FCM_O  (FVT_O + 2 * FKS_B)    // 36864
#define FCL_O  (FCM_O + 1024)         // 37888
#define FLASH_SMEM (FCL_O + 1024)     // 38912 B

__global__ __launch_bounds__(256) void flash_mma(
    const __half* __restrict__ Q, const __half* __restrict__ K,
    const __half* __restrict__ V, __half* __restrict__ ctx)
{
    extern __shared__ char smraw[];
    float*  cm = (float*)(smraw + FCM_O);   // [2][128]
    float*  cl = (float*)(smraw + FCL_O);   // [2][128]
    float*  ac = (float*)smraw;             // epilogue alias, stride 66
    const uint32_t Ks_u = smem_u32(smraw);
    const uint32_t Vs_u = Ks_u + FVT_O;

    const int qi   = gridDim.x - 1 - blockIdx.x;   // heavy tiles first
    const int bh   = blockIdx.y;
    const int tid  = threadIdx.x;
    const int lane = tid & 31;
    const int wid  = tid >> 5;
    const int wr   = wid & 3;
    const int wc   = wid >> 2;
    const int lq   = lane >> 2;
    const int ls   = lane & 3;
    const int s    = lane >> 3;
    const int srow = lane & 7;
    const int row0 = wr * 32;

    const uint32_t bk_lane =
        (uint32_t)((s >> 1) * 8 + srow) * KSTRB + (s & 1) * 16;
    const uint32_t bv_lane =
        (uint32_t)((s & 1) * 8 + srow) * KSTRB + (s >> 1) * 16;

    const __half* Qb = Q + ((size_t)bh * LL + qi * 128) * HD;
    const __half* Kb = K + (size_t)bh * LL * HD;
    const __half* Vb = V + (size_t)bh * LL * HD;

#define FL_LOAD_T(dst_u, src)                                                 \
    {                                                                         \
        _Pragma("unroll")                                                     \
        for (int i = 0; i < 2; ++i) {                                         \
            const int c   = tid + i * 256;                                    \
            const int row = c >> 3;                                           \
            const int cc  = (c & 7) * 8;                                      \
            CP16((dst_u) + (uint32_t)row * KSTRB + cc * 2,                    \
                 (src) + (size_t)row * HD + cc);                              \
        }                                                                     \
    }

    FL_LOAD_T(Ks_u, Kb);
    FL_LOAD_T(Vs_u, Vb);
    CP_COMMIT();

    uint32_t qf[4][2][4];
#pragma unroll
    for (int ks = 0; ks < 4; ++ks) {
#pragma unroll
        for (int mt = 0; mt < 2; ++mt) {
            const int r = row0 + mt * 16 + lq;
            const __half* q0 = Qb + (size_t)r * HD + ks * 16;
            const __half* q1 = Qb + (size_t)(r + 8) * HD + ks * 16;
            qf[ks][mt][0] = *(const uint32_t*)(q0 + 2 * ls);
            qf[ks][mt][1] = *(const uint32_t*)(q1 + 2 * ls);
            qf[ks][mt][2] = *(const uint32_t*)(q0 + 8 + 2 * ls);
            qf[ks][mt][3] = *(const uint32_t*)(q1 + 8 + 2 * ls);
        }
    }

    float acc[2][8][4];
#pragma unroll
    for (int mt = 0; mt < 2; ++mt)
#pragma unroll
        for (int nt = 0; nt < 8; ++nt)
#pragma unroll
            for (int r = 0; r < 4; ++r) acc[mt][nt][r] = 0.f;
    float mm[4] = {-1e30f, -1e30f, -1e30f, -1e30f};
    float llv[4] = {0.f, 0.f, 0.f, 0.f};

    const int jtmax = 2 * qi + 1;

    for (int jt = 0; jt <= jtmax; ++jt) {
        const int db = jt & 1;
        CP_WAIT(0);
        __syncthreads();

        if (jt < jtmax) {
            FL_LOAD_T(Ks_u + (uint32_t)((db ^ 1) * FKS_B),
                      Kb + (size_t)(jt + 1) * 64 * HD);
            FL_LOAD_T(Vs_u + (uint32_t)((db ^ 1) * FKS_B),
                      Vb + (size_t)(jt + 1) * 64 * HD);
            CP_COMMIT();
        }

        float sc[2][4][4];
#pragma unroll
        for (int mt = 0; mt < 2; ++mt)
#pragma unroll
            for (int nt = 0; nt < 4; ++nt)
#pragma unroll
                for (int r = 0; r < 4; ++r) sc[mt][nt][r] = 0.f;

        const uint32_t Kd_u = Ks_u + (uint32_t)(db * FKS_B)
                            + (uint32_t)(wc * 32) * KSTRB + bk_lane;
#pragma unroll
        for (int ks = 0; ks < 4; ++ks) {
#pragma unroll
            for (int ntp = 0; ntp < 2; ++ntp) {
                uint32_t b[4];
                ldsm4(b, Kd_u + (uint32_t)(ntp * 16) * KSTRB + ks * 32);
#pragma unroll
                for (int mt = 0; mt < 2; ++mt) {
                    mma16(sc[mt][ntp * 2],     qf[ks][mt], b);
                    mma16(sc[mt][ntp * 2 + 1], qf[ks][mt], b + 2);
                }
            }
        }

        if (jt >= 2 * qi) {
            const int cbase = jt * 64 + wc * 32;
#pragma unroll
            for (int mt = 0; mt < 2; ++mt) {
                const int rg0 = qi * 128 + row0 + mt * 16 + lq;
#pragma unroll
                for (int nt = 0; nt < 4; ++nt) {
                    const int cg = cbase + nt * 8 + ls * 2;
                    if (cg > rg0)         sc[mt][nt][0] += -1000000000.0f;
                    if (cg + 1 > rg0)     sc[mt][nt][1] += -1000000000.0f;
                    if (cg > rg0 + 8)     sc[mt][nt][2] += -1000000000.0f;
                    if (cg + 1 > rg0 + 8) sc[mt][nt][3] += -1000000000.0f;
                }
            }
        }

        float mx[4];
#pragma unroll
        for (int mt = 0; mt < 2; ++mt) {
            float a0 = sc[mt][0][0], a1 = sc[mt][0][2];
#pragma unroll
            for (int nt = 0; nt < 4; ++nt) {
                a0 = fmaxf(a0, fmaxf(sc[mt][nt][0], sc[mt][nt][1]));
                a1 = fmaxf(a1, fmaxf(sc[mt][nt][2], sc[mt][nt][3]));
            }
            mx[mt * 2]     = a0;
            mx[mt * 2 + 1] = a1;
        }
#pragma unroll
        for (int i = 0; i < 4; ++i) {
            mx[i] = fmaxf(mx[i], __shfl_xor_sync(0xffffffffu, mx[i], 1));
            mx[i] = fmaxf(mx[i], __shfl_xor_sync(0xffffffffu, mx[i], 2));
        }

        float al[4];
#pragma unroll
        for (int i = 0; i < 4; ++i) {
            const float mn = fmaxf(mm[i], mx[i]);
            al[i] = __expf(mm[i] - mn);
            mm[i] = mn;
        }

        uint32_t pa[2][2][4];
        float rs[4] = {0.f, 0.f, 0.f, 0.f};
#pragma unroll
        for (int mt = 0; mt < 2; ++mt) {
            const float mn0 = mm[mt * 2], mn1 = mm[mt * 2 + 1];
#pragma unroll
            for (int nt = 0; nt < 4; ++nt) {
                const float p0 = __expf(sc[mt][nt][0] - mn0);
                const float p1 = __expf(sc[mt][nt][1] - mn0);
                const float p2 = __expf(sc[mt][nt][2] - mn1);
                const float p3 = __expf(sc[mt][nt][3] - mn1);
                rs[mt * 2]     += p0 + p1;
                rs[mt * 2 + 1] += p2 + p3;
                pa[mt][nt >> 1][(nt & 1) * 2 + 0] = pack_h2(p0, p1);
                pa[mt][nt >> 1][(nt & 1) * 2 + 1] = pack_h2(p2, p3);
            }
        }
#pragma unroll
        for (int i = 0; i < 4; ++i) {
            rs[i] += __shfl_xor_sync(0xffffffffu, rs[i], 1);
            rs[i] += __shfl_xor_sync(0xffffffffu, rs[i], 2);
            llv[i] = llv[i] * al[i] + rs[i];
        }

#pragma unroll
        for (int mt = 0; mt < 2; ++mt)
#pragma unroll
            for (int nt = 0; nt < 8; ++nt) {
                acc[mt][nt][0] *= al[mt * 2];     acc[mt][nt][1] *= al[mt * 2];
                acc[mt][nt][2] *= al[mt * 2 + 1]; acc[mt][nt][3] *= al[mt * 2 + 1];
            }

        const uint32_t Vd_u = Vs_u + (uint32_t)(db * FKS_B) + bv_lane;
#pragma unroll
        for (int ks = 0; ks < 2; ++ks) {
            const uint32_t vtok_off =
                (uint32_t)(wc * 32 + ks * 16) * KSTRB;
#pragma unroll
            for (int ntp = 0; ntp < 4; ++ntp) {
                uint32_t b[4];
                ldsm4t(b, Vd_u + vtok_off + (uint32_t)(ntp * 16) * 2);
#pragma unroll
                for (int mt = 0; mt < 2; ++mt) {
                    mma16(acc[mt][ntp * 2],     pa[mt][ks], b);
                    mma16(acc[mt][ntp * 2 + 1], pa[mt][ks], b + 2);
                }
            }
        }
    }

    if (ls == 0) {
#pragma unroll
        for (int mt = 0; mt < 2; ++mt) {
            const int r = row0 + mt * 16 + lq;
            cm[wc * 128 + r]     = mm[mt * 2];
            cm[wc * 128 + r + 8] = mm[mt * 2 + 1];
            cl[wc * 128 + r]     = llv[mt * 2];
            cl[wc * 128 + r + 8] = llv[mt * 2 + 1];
        }
    }
    __syncthreads();

    float sS[4], lt[4];
#pragma unroll
    for (int i = 0; i < 4; ++i) {
        const int row = row0 + (i >> 1) * 16 + (i & 1) * 8 + lq;
        const float mo = cm[(wc ^ 1) * 128 + row];
        const float lo = cl[(wc ^ 1) * 128 + row];
        const float M  = fmaxf(mm[i], mo);
        sS[i] = __expf(mm[i] - M);
        lt[i] = llv[i] * sS[i] + lo * __expf(mo - M);
    }

    if (wc == 1) {
#pragma unroll
        for (int mt = 0; mt < 2; ++mt) {
            const int r = row0 + mt * 16 + lq;
#pragma unroll
            for (int nt = 0; nt < 8; ++nt) {
                const int cc = nt * 8 + ls * 2;
                float2 w0, w1;
                w0.x = acc[mt][nt][0] * sS[mt * 2];
                w0.y = acc[mt][nt][1] * sS[mt * 2];
                w1.x = acc[mt][nt][2] * sS[mt * 2 + 1];
                w1.y = acc[mt][nt][3] * sS[mt * 2 + 1];
                *(float2*)(ac + r * 66 + cc)       = w0;
                *(float2*)(ac + (r + 8) * 66 + cc) = w1;
            }
        }
    }
    __syncthreads();

    if (wc == 0) {
        const int b = bh >> 4;
        const int h = bh & 15;
#pragma unroll
        for (int mt = 0; mt < 2; ++mt) {
            const float inv0 = 1.f / lt[mt * 2];
            const float inv1 = 1.f / lt[mt * 2 + 1];
            const int r  = row0 + mt * 16 + lq;
            const int rg = qi * 128 + r;
#pragma unroll
            for (int nt = 0; nt < 8; ++nt) {
                const int cc = nt * 8 + ls * 2;
                const float2 p0 = *(const float2*)(ac + r * 66 + cc);
                const float2 p1 = *(const float2*)(ac + (r + 8) * 66 + cc);
                const int cn = h * HD + cc;
                const uint32_t o0 = pack_h2(
                    (acc[mt][nt][0] * sS[mt * 2] + p0.x) * inv0,
                    (acc[mt][nt][1] * sS[mt * 2] + p0.y) * inv0);
                const uint32_t o1 = pack_h2(
                    (acc[mt][nt][2] * sS[mt * 2 + 1] + p1.x) * inv1,
                    (acc[mt][nt][3] * sS[mt * 2 + 1] + p1.y) * inv1);
                *(uint32_t*)(ctx + (size_t)(b * LL + rg) * DD + cn)     = o0;
                *(uint32_t*)(ctx + (size_t)(b * LL + rg + 8) * DD + cn) = o1;
            }
        }
    }
}

// ---------------------------------------------------------------------------
// Launch
// ---------------------------------------------------------------------------
extern "C" void kernel_launch(void* const* d_in, const int* in_sizes, int n_in,
                              void* d_out, int out_size)
{
    const float* x       = (const float*)d_in[0];
    const float* Wqkv_w  = (const float*)d_in[2];
    const float* Wqkv_b  = (const float*)d_in[3];
    const float* Wout_w  = (const float*)d_in[4];
    const float* Wout_b  = (const float*)d_in[5];

    float* out  = (float*)d_out;
    float* kout = out + BLD;
    float* vout = kout + BLD;

    __half *xr, *wqkv, *wout_r, *qh, *kh, *vh, *ctx;
    cudaGetSymbolAddress((void**)&xr,     g_xr);
    cudaGetSymbolAddress((void**)&wqkv,   g_wqkv);
    cudaGetSymbolAddress((void**)&wout_r, g_wout);
    cudaGetSymbolAddress((void**)&qh,     g_q);
    cudaGetSymbolAddress((void**)&kh,     g_k);
    cudaGetSymbolAddress((void**)&vh,     g_v);
    cudaGetSymbolAddress((void**)&ctx,    g_ctx);

    cudaFuncSetAttribute(gemm_qkv_rope,
                         cudaFuncAttributeMaxDynamicSharedMemorySize, QKV_SMEM);
    cudaFuncSetAttribute(gemm_out,
                         cudaFuncAttributeMaxDynamicSharedMemorySize, GEMM_PIPE_B);
    cudaFuncSetAttribute(flash_mma,
                         cudaFuncAttributeMaxDynamicSharedMemorySize, FLASH_SMEM);

    round_all<<<(RND_TOTAL4 + 255) / 256, 256>>>(
        (const float4*)x, xr,
        (const float4*)Wqkv_w, wqkv,
        (const float4*)Wout_w, wout_r);

    gemm_qkv_rope<<<dim3(QKV_N / 128, ROWS / 128), 256, QKV_SMEM>>>(
        xr, wqkv, Wqkv_b, qh, kh, vh, kout, vout);

    flash_mma<<<dim3(LL / 128, BB * HH), 256, FLASH_SMEM>>>(qh, kh, vh, ctx);

    gemm_out<<<dim3(DD / 128, ROWS / 128), 256, GEMM_PIPE_B>>>(
        ctx, wout_r, Wout_b, out, DD);
}